// round 7
// baseline (speedup 1.0000x reference)
#include <cuda_runtime.h>

// RMSNorm over last axis: x[32768 rows, 2048] fp32, weight[2048] fp32.
// One CTA per row, 256 threads, 8 floats/thread register-resident.
// Single pass: load (streaming) -> reduce sum(x^2) -> rsqrt -> scale -> store (streaming).
// HBM-bound: 512 MiB total traffic, roofline floor ~65-75 us on GB300.
// Single-barrier reduction: after warp sums land in smem, every thread
// redundantly sums the 8 values (LDS broadcast) and computes its own rsqrt,
// eliminating the second __syncthreads.

#define ROW_LEN 2048
#define THREADS 256
#define NWARPS  (THREADS / 32)

__global__ __launch_bounds__(THREADS)
void rmsnorm_kernel(const float* __restrict__ x,
                    const float* __restrict__ w,
                    float* __restrict__ out)
{
    const size_t row = blockIdx.x;
    const float4* __restrict__ xr = reinterpret_cast<const float4*>(x + row * ROW_LEN);
    float4* __restrict__ outr     = reinterpret_cast<float4*>(out + row * ROW_LEN);
    const float4* __restrict__ w4 = reinterpret_cast<const float4*>(w);

    const int t = threadIdx.x;

    // Front-batched 128-bit streaming loads (evict-first: zero reuse of x).
    float4 v0 = __ldcs(&xr[t]);
    float4 v1 = __ldcs(&xr[t + THREADS]);

    // Weight loads issued early (L2-resident, 8 KB shared by all CTAs) so their
    // latency overlaps the reduction below.
    float4 w0 = __ldg(&w4[t]);
    float4 w1 = __ldg(&w4[t + THREADS]);

    // Per-thread sum of squares.
    float ss = v0.x * v0.x + v0.y * v0.y + v0.z * v0.z + v0.w * v0.w
             + v1.x * v1.x + v1.y * v1.y + v1.z * v1.z + v1.w * v1.w;

    // Warp reduce.
    #pragma unroll
    for (int off = 16; off > 0; off >>= 1)
        ss += __shfl_xor_sync(0xFFFFFFFFu, ss, off);

    // Cross-warp reduce: one barrier, then every thread sums the 8 warp
    // partials itself (broadcast LDS, conflict-free) and computes rsqrt.
    __shared__ float warp_sums[NWARPS];
    const int lane = t & 31;
    const int wid  = t >> 5;
    if (lane == 0) warp_sums[wid] = ss;
    __syncthreads();

    float s = 0.0f;
    #pragma unroll
    for (int i = 0; i < NWARPS; i++)
        s += warp_sums[i];

    const float inv = rsqrtf(s * (1.0f / (float)ROW_LEN) + 1e-6f);

    float4 o0, o1;
    o0.x = v0.x * inv * w0.x;  o0.y = v0.y * inv * w0.y;
    o0.z = v0.z * inv * w0.z;  o0.w = v0.w * inv * w0.w;
    o1.x = v1.x * inv * w1.x;  o1.y = v1.y * inv * w1.y;
    o1.z = v1.z * inv * w1.z;  o1.w = v1.w * inv * w1.w;

    // Streaming stores (evict-first: output not re-read).
    __stcs(&outr[t],           o0);
    __stcs(&outr[t + THREADS], o1);
}

extern "C" void kernel_launch(void* const* d_in, const int* in_sizes, int n_in,
                              void* d_out, int out_size)
{
    const float* x = (const float*)d_in[0];
    const float* w = (const float*)d_in[1];
    float* out     = (float*)d_out;

    const int rows = out_size / ROW_LEN;  // 32768
    rmsnorm_kernel<<<rows, THREADS>>>(x, w, out);
}